// round 16
// baseline (speedup 1.0000x reference)
#include <cuda_runtime.h>

#define HH 1024
#define WW 1024
#define NPIX (HH * WW)
#define NB 8
#define NBLK 256    // stats tiles per plane: 8 x 32 (128x32)
#define NCONVT 128  // conv tiles per plane: 8 x 16 (128x64)

#define P_ 0.19487471f   // sqrt(0.03797616)
#define Q_ 0.23021729f   // sqrt(0.053); outer([p,q,p],[p,q,p]) == reference 3x3
#define WFULL 0xffffffffu

__device__ float    g_buf[2][2][NB * NPIX];
__device__ float    g_part[NB][5][NBLK];
__device__ unsigned g_barcnt;
__device__ volatile unsigned g_sense;
__device__ unsigned g_taskctr[4];

struct TileC {                      // conv tasks: 128x64 out, halo-2
    float h1[68][128];
    float elo[68], ehi[68];
};
struct TileS {                      // stats tasks: 128x32 out, x then y
    float h1[36][128];
    float ox[32][128];              // staged x-conv output
    float elo[36], ehi[36];
};
#define SMEM_BYTES (sizeof(TileC) > sizeof(TileS) ? sizeof(TileC) : sizeof(TileS))

__inline__ __device__ float warpSumF(float v) {
#pragma unroll
    for (int o = 16; o; o >>= 1) v += __shfl_down_sync(WFULL, v, o);
    return v;
}
__inline__ __device__ double warpSumD(double v) {
#pragma unroll
    for (int o = 16; o; o >>= 1) v += __shfl_down_sync(WFULL, v, o);
    return v;
}

__device__ __forceinline__ float4 vpass(float4 a, float4 b, float4 c) {
    return make_float4(P_ * (a.x + c.x) + Q_ * b.x,
                       P_ * (a.y + c.y) + Q_ * b.y,
                       P_ * (a.z + c.z) + Q_ * b.z,
                       P_ * (a.w + c.w) + Q_ * b.w);
}

// ---- row load: thread's float4 of row gy + edge scalars for lanes 0/31 ----
// NCH==3: raw inputs (immutable) -> normal cached loads.
// NCH==1: ping-pong scratch written by OTHER SMs across the software
//         barrier -> must bypass L1 (__ldcg); per-SM L1 is not coherent.
template <int NCH>
__device__ __forceinline__ float4 load_row(const float* __restrict__ s, int gy,
                                           int x0, int lane, float& e0, float& e1) {
    e0 = 0.f; e1 = 0.f;
    if ((unsigned)gy >= HH) return make_float4(0.f, 0.f, 0.f, 0.f);
    const float* r = s + (size_t)gy * WW;
    const float* q = r + x0 + lane * 4;
    float4 a;
    if (NCH == 3) {
        a = *(const float4*)q;
        float4 b = *(const float4*)(q + NPIX);
        float4 c = *(const float4*)(q + 2 * NPIX);
        a.x += b.x + c.x; a.y += b.y + c.y; a.z += b.z + c.z; a.w += b.w + c.w;
    } else {
        a = __ldcg((const float4*)q);
    }
    if (lane == 0) {
        if (x0 > 0) {
            if (NCH == 3) {
                e0 = r[x0 - 2] + r[x0 - 2 + NPIX] + r[x0 - 2 + 2 * NPIX];
                e1 = r[x0 - 1] + r[x0 - 1 + NPIX] + r[x0 - 1 + 2 * NPIX];
            } else {
                e0 = __ldcg(r + x0 - 2);
                e1 = __ldcg(r + x0 - 1);
            }
        }
    } else if (lane == 31) {
        if (x0 < WW - 128) {
            if (NCH == 3) {
                e0 = r[x0 + 128] + r[x0 + 128 + NPIX] + r[x0 + 128 + 2 * NPIX];
                e1 = r[x0 + 129] + r[x0 + 129 + NPIX] + r[x0 + 129 + 2 * NPIX];
            } else {
                e0 = __ldcg(r + x0 + 128);
                e1 = __ldcg(r + x0 + 129);
            }
        }
    }
    return a;
}

// ---- horizontal conv of a register row via shuffles ----------------------
__device__ __forceinline__ float4 hshuf(float4 x, float e0, float e1, int lane) {
    float xl = __shfl_up_sync(WFULL, x.w, 1);   if (lane == 0)  xl = e1;
    float xr = __shfl_down_sync(WFULL, x.x, 1); if (lane == 31) xr = e0;
    return make_float4(P_ * (xl + x.y) + Q_ * x.x,
                       P_ * (x.x + x.z) + Q_ * x.y,
                       P_ * (x.y + x.w) + Q_ * x.z,
                       P_ * (x.z + xr) + Q_ * x.w);
}

// ---- generic h1 store (NR rows) -------------------------------------------
template <int NCH, int NR, bool EDGES>
__device__ __forceinline__ void h1_store(float (*h1)[128], float* elo, float* ehi,
                                         const float* __restrict__ src,
                                         int x0, int ytop, int lane, int w) {
#pragma unroll
    for (int k = 0; k < (NR + 7) / 8; k++) {
        int r = w + 8 * k;
        if (r < NR) {
            float e0, e1;
            float4 x = load_row<NCH>(src, ytop + r, x0, lane, e0, e1);
            float4 h = hshuf(x, e0, e1, lane);
            *(float4*)&h1[r][4 * lane] = h;
            if (EDGES) {
                if (lane == 0)  elo[r] = P_ * (e0 + x.x) + Q_ * e1;  // col -1
                if (lane == 31) ehi[r] = P_ * (x.w + e1) + Q_ * e0;  // col 128
            }
        }
    }
}

// ---- h2 row rv (gv = y0-1+rv) from h1 rows rv..rv+2 -----------------------
__device__ __forceinline__ float4 h2row_ld(const float (*h1)[128],
                                           const float* elo, const float* ehi,
                                           int rv, int y0, int lane,
                                           bool xlo, bool xhi) {
    float4 a0 = *(float4*)&h1[rv][4 * lane];
    float4 a1 = *(float4*)&h1[rv + 1][4 * lane];
    float4 a2 = *(float4*)&h1[rv + 2][4 * lane];
    float4 v = vpass(a0, a1, a2);
    float ve = 0.f;
    if (lane == 0)
        ve = P_ * (elo[rv] + elo[rv + 2]) + Q_ * elo[rv + 1];
    else if (lane == 31)
        ve = P_ * (ehi[rv] + ehi[rv + 2]) + Q_ * ehi[rv + 1];
    int gv = y0 - 1 + rv;
    if ((unsigned)gv >= HH) { v = make_float4(0.f, 0.f, 0.f, 0.f); ve = 0.f; }
    if (lane == 0 && xlo)  ve = 0.f;   // col -1 outside image
    if (lane == 31 && xhi) ve = 0.f;   // col 1024 outside image
    float vl = __shfl_up_sync(WFULL, v.w, 1);   if (lane == 0)  vl = ve;
    float vr = __shfl_down_sync(WFULL, v.x, 1); if (lane == 31) vr = ve;
    float4 g;
    g.x = P_ * (vl + v.y) + Q_ * v.x;
    g.y = P_ * (v.x + v.z) + Q_ * v.y;
    g.z = P_ * (v.y + v.w) + Q_ * v.z;
    g.w = P_ * (v.z + vr) + Q_ * v.w;
    return g;
}

// ---- conv epilogue: warp w writes output rows y0+8w .. y0+8w+7 ------------
__device__ void conv_epi(TileC* S, float* __restrict__ dst, int x0, int y0,
                         int lane, int w, bool xlo, bool xhi) {
    const int base = 8 * w;
    float4 g0 = h2row_ld(S->h1, S->elo, S->ehi, base, y0, lane, xlo, xhi);
    float4 g1 = h2row_ld(S->h1, S->elo, S->ehi, base + 1, y0, lane, xlo, xhi);
#pragma unroll
    for (int j = 0; j < 8; j++) {
        float4 g2 = h2row_ld(S->h1, S->elo, S->ehi, base + j + 2, y0, lane, xlo, xhi);
        float4 o = vpass(g0, g1, g2);
        *(float4*)(dst + (size_t)(y0 + base + j) * WW + x0 + 4 * lane) = o;
        g0 = g1; g1 = g2;
    }
}

// ---- moments ---------------------------------------------------------------
__device__ __forceinline__ void mom_acc(float4 a, float4 b, float& su, float& su2,
                                        float& sv, float& sv2, float& suv) {
    su  += a.x + a.y + a.z + a.w;
    su2 += a.x * a.x + a.y * a.y + a.z * a.z + a.w * a.w;
    sv  += b.x + b.y + b.z + b.w;
    sv2 += b.x * b.x + b.y * b.y + b.z * b.z + b.w * b.w;
    suv += a.x * b.x + a.y * b.y + a.z * b.z + a.w * b.w;
}

// ---- stats x-pass epilogues: conv result staged into S->ox ----------------
__device__ void stats_x_single(TileS* S, int lane, int w) {
    const int b = 4 * w;
#pragma unroll
    for (int j = 0; j < 4; j++) {
        float4 a0 = *(float4*)&S->h1[b + j][4 * lane];
        float4 a1 = *(float4*)&S->h1[b + j + 1][4 * lane];
        float4 a2 = *(float4*)&S->h1[b + j + 2][4 * lane];
        *(float4*)&S->ox[b + j][4 * lane] = vpass(a0, a1, a2);
    }
}
__device__ void stats_x_double(TileS* S, int y0, int lane, int w,
                               bool xlo, bool xhi) {
    const int b = 4 * w;
    float4 g0, g1;
#pragma unroll
    for (int m = 0; m < 6; m++) {
        float4 g2 = h2row_ld(S->h1, S->elo, S->ehi, b + m, y0, lane, xlo, xhi);
        if (m >= 2)
            *(float4*)&S->ox[b + m - 2][4 * lane] = vpass(g0, g1, g2);
        g0 = g1; g1 = g2;
    }
}

// ---- stats y-pass epilogues: accumulate moments against staged ox ---------
__device__ void stats_y_single(TileS* S, int lane, int w, float& su, float& su2,
                               float& sv, float& sv2, float& suv) {
    const int b = 4 * w;
#pragma unroll
    for (int j = 0; j < 4; j++) {
        float4 a0 = *(float4*)&S->h1[b + j][4 * lane];
        float4 a1 = *(float4*)&S->h1[b + j + 1][4 * lane];
        float4 a2 = *(float4*)&S->h1[b + j + 2][4 * lane];
        float4 oy = vpass(a0, a1, a2);
        float4 ox = *(float4*)&S->ox[b + j][4 * lane];   // same-warp rows
        mom_acc(ox, oy, su, su2, sv, sv2, suv);
    }
}
__device__ void stats_y_double(TileS* S, int y0, int lane, int w,
                               bool xlo, bool xhi, float& su, float& su2,
                               float& sv, float& sv2, float& suv) {
    const int b = 4 * w;
    float4 g0, g1;
#pragma unroll
    for (int m = 0; m < 6; m++) {
        float4 g2 = h2row_ld(S->h1, S->elo, S->ehi, b + m, y0, lane, xlo, xhi);
        if (m >= 2) {
            float4 oy = vpass(g0, g1, g2);
            float4 ox = *(float4*)&S->ox[b + m - 2][4 * lane];
            mom_acc(ox, oy, su, su2, sv, sv2, suv);
        }
        g0 = g1; g1 = g2;
    }
}

// ---- global software barrier ---------------------------------------------
__device__ __forceinline__ void gbar(int nblocks, unsigned phase, int tid) {
    __syncthreads();
    if (tid == 0) {
        __threadfence();
        unsigned c = atomicAdd(&g_barcnt, 1u);
        if (c == (unsigned)nblocks - 1u) {
            g_barcnt = 0;
            __threadfence();
            g_sense = phase;
        } else {
            while (g_sense < phase) __nanosleep(64);
            __threadfence();
        }
    }
    __syncthreads();
}

// ---- finalize: 8 SSIM terms in double (block 0) --------------------------
__device__ void finalize_dev(float* __restrict__ out, int tid) {
    __shared__ double smd[NB][5];
    const int w = tid >> 5, lane = tid & 31;
    for (int idx = w; idx < NB * 5; idx += 8) {
        int t = idx / 5, m = idx - 5 * t;
        double s = 0.0;
        for (int b = lane; b < NBLK; b += 32)
            s += (double)__ldcg(&g_part[t][m][b]);   // cross-SM data: bypass L1
        s = warpSumD(s);
        if (lane == 0) smd[t][m] = s;
    }
    __syncthreads();
    if (tid == 0) {
        double tot = 0.0, sc = 1.0;
        const double N = (double)NPIX;
        const double C1 = 6.5025;    // (0.01*255)^2
        const double C2 = 58.5225;   // (0.03*255)^2
        for (int t = 0; t < NB; t++) {
            double SU = smd[t][0], SU2 = smd[t][1], SV = smd[t][2],
                   SV2 = smd[t][3], SUV = smd[t][4];
            double mu = sc * SU / N;
            double mv = sc * SV / N;
            double varu = sc * sc * (SU2 - SU * SU / N) / (N - 1.0);
            double varv = sc * sc * (SV2 - SV * SV / N) / (N - 1.0);
            double cov  = sc * sc * (SUV - SU * SV / N) / (N - 1.0);
            tot += ((2.0 * mu * mv + C1) * (2.0 * cov + C2)) /
                   ((mu * mu + mv * mv + C1) * (varu * varu + varv * varv + C2));
            sc *= 3.0;   // 3^t channel-mixing gain
        }
        out[0] = (float)tot;
    }
}

// ---------------------------------------------------------------------------
// Persistent kernel: 4 pair-phases with global barriers; work-stealing with
// pipelined ticket fetch. 42-reg cap -> 6 blocks/SM (75% occ target).
// ---------------------------------------------------------------------------
__global__ void __launch_bounds__(256, 6)
ssim_persist(const float* __restrict__ xin, const float* __restrict__ yin,
             float* __restrict__ out, int nblocks) {
    __shared__ __align__(16) char smem_raw[SMEM_BYTES];
    __shared__ float s_red[5][8];     // separate: written/read around final sync
    __shared__ unsigned s_task;
    TileC* Sc = (TileC*)smem_raw;
    TileS* Ss = (TileS*)smem_raw;
    const int tid = threadIdx.x, lane = tid & 31, w = tid >> 5;

    for (int p = 0; p < 4; p++) {
        const int t0 = 2 * p, nimg = NB - t0;
        const int rp = (p & 1) ^ 1, wp = p & 1;
        const unsigned nstats = 2u * NBLK;
        const unsigned ntasks = nstats + (unsigned)(2 * (nimg - 2)) * NCONVT;

        if (tid == 0) s_task = atomicAdd(&g_taskctr[p], 1u);
        __syncthreads();
        unsigned task = s_task;

        while (task < ntasks) {
            if (task >= nstats) {
                // ---- conv task: 128x64 tile ----
                const unsigned ct = task - nstats;
                const int plane2 = (int)(ct >> 7), tile = (int)(ct & 127);
                const int x0 = (tile & 7) * 128;
                const int y0 = (tile >> 3) * 64;
                const bool xlo = (x0 == 0), xhi = (x0 == WW - 128);
                int xy = (plane2 >= nimg - 2) ? 1 : 0;
                int img = t0 + 2 + plane2 - xy * (nimg - 2);
                const float* src = (p == 0)
                    ? ((xy ? yin : xin) + (size_t)img * 3 * NPIX)
                    : (g_buf[rp][xy] + (size_t)img * NPIX);
                float* dst = g_buf[wp][xy] + (size_t)img * NPIX;

                if (p == 0) h1_store<3, 68, true>(Sc->h1, Sc->elo, Sc->ehi, src, x0, y0 - 2, lane, w);
                else        h1_store<1, 68, true>(Sc->h1, Sc->elo, Sc->ehi, src, x0, y0 - 2, lane, w);
                if (tid == 0) s_task = atomicAdd(&g_taskctr[p], 1u);  // pipelined
                __syncthreads();   // h1 ready + ticket published
                conv_epi(Sc, dst, x0, y0, lane, w, xlo, xhi);
                unsigned nxt = s_task;
                __syncthreads();   // epilogue done; smem free for next task
                task = nxt;
            } else {
                // ---- stats task: 128x32 tile, x staged then y ----
                const int plane = (int)(task >> 8), tile = (int)(task & 255);
                const int x0 = (tile & 7) * 128;
                const int y0 = (tile >> 3) * 32;
                const bool xlo = (x0 == 0), xhi = (x0 == WW - 128);
                const int t = t0 + plane;
                const float *sx, *sy;
                if (p == 0) {
                    sx = xin + (size_t)t * 3 * NPIX;
                    sy = yin + (size_t)t * 3 * NPIX;
                } else {
                    sx = g_buf[rp][0] + (size_t)t * NPIX;
                    sy = g_buf[rp][1] + (size_t)t * NPIX;
                }
                // ---- x pass ----
                if (plane == 0) {
                    if (p == 0) h1_store<3, 34, false>(Ss->h1, Ss->elo, Ss->ehi, sx, x0, y0 - 1, lane, w);
                    else        h1_store<1, 34, false>(Ss->h1, Ss->elo, Ss->ehi, sx, x0, y0 - 1, lane, w);
                } else {
                    if (p == 0) h1_store<3, 36, true>(Ss->h1, Ss->elo, Ss->ehi, sx, x0, y0 - 2, lane, w);
                    else        h1_store<1, 36, true>(Ss->h1, Ss->elo, Ss->ehi, sx, x0, y0 - 2, lane, w);
                }
                __syncthreads();   // A: h1(x) ready
                if (plane == 0) stats_x_single(Ss, lane, w);
                else            stats_x_double(Ss, y0, lane, w, xlo, xhi);
                __syncthreads();   // B: x epilogue done; h1 reusable
                // ---- y pass ----
                if (plane == 0) {
                    if (p == 0) h1_store<3, 34, false>(Ss->h1, Ss->elo, Ss->ehi, sy, x0, y0 - 1, lane, w);
                    else        h1_store<1, 34, false>(Ss->h1, Ss->elo, Ss->ehi, sy, x0, y0 - 1, lane, w);
                } else {
                    if (p == 0) h1_store<3, 36, true>(Ss->h1, Ss->elo, Ss->ehi, sy, x0, y0 - 2, lane, w);
                    else        h1_store<1, 36, true>(Ss->h1, Ss->elo, Ss->ehi, sy, x0, y0 - 2, lane, w);
                }
                if (tid == 0) s_task = atomicAdd(&g_taskctr[p], 1u);  // pipelined
                __syncthreads();   // C: h1(y) ready + ticket published

                float su = 0, su2 = 0, sv = 0, sv2 = 0, suv = 0;
                if (plane == 0) stats_y_single(Ss, lane, w, su, su2, sv, sv2, suv);
                else stats_y_double(Ss, y0, lane, w, xlo, xhi, su, su2, sv, sv2, suv);

                su = warpSumF(su); su2 = warpSumF(su2); sv = warpSumF(sv);
                sv2 = warpSumF(sv2); suv = warpSumF(suv);
                if (lane == 0) {
                    s_red[0][w] = su; s_red[1][w] = su2; s_red[2][w] = sv;
                    s_red[3][w] = sv2; s_red[4][w] = suv;
                }
                unsigned nxt = s_task;
                __syncthreads();   // D: red ready; tile smem free for next task
                if (tid < 5) {
                    float r = 0.f;
#pragma unroll
                    for (int q = 0; q < 8; q++) r += s_red[tid][q];
                    g_part[t][tid][tile] = r;
                }
                task = nxt;
            }
        }
        gbar(nblocks, (unsigned)(p + 1), tid);
    }

    if (blockIdx.x == 0) {
        finalize_dev(out, tid);
        if (tid == 0) {
            g_taskctr[0] = 0; g_taskctr[1] = 0;
            g_taskctr[2] = 0; g_taskctr[3] = 0;
            __threadfence();
            g_sense = 0;   // reset for next graph replay
        }
    }
}

// ---------------------------------------------------------------------------
extern "C" void kernel_launch(void* const* d_in, const int* in_sizes, int n_in,
                              void* d_out, int out_size) {
    const float* x = (const float*)d_in[0];
    const float* y = (const float*)d_in[1];
    float* out = (float*)d_out;

    int dev = 0;
    cudaGetDevice(&dev);
    int sms = 148;
    cudaDeviceGetAttribute(&sms, cudaDevAttrMultiProcessorCount, dev);
    int occ = 1;
    cudaOccupancyMaxActiveBlocksPerMultiprocessor(&occ, ssim_persist, 256, 0);
    if (occ < 1) occ = 1;
    int nblocks = sms * occ;

    ssim_persist<<<nblocks, 256>>>(x, y, out, nblocks);
}

// round 17
// speedup vs baseline: 1.1063x; 1.1063x over previous
#include <cuda_runtime.h>

#define HH 1024
#define WW 1024
#define NPIX (HH * WW)
#define NB 8
#define NBLK 256    // stats tiles per plane: 8 x 32 (128x32)
#define NCONVT 128  // conv tiles per plane: 8 x 16 (128x64)

#define P_ 0.19487471f   // sqrt(0.03797616)
#define Q_ 0.23021729f   // sqrt(0.053); outer([p,q,p],[p,q,p]) == reference 3x3
#define WFULL 0xffffffffu

__device__ float    g_buf[2][2][NB * NPIX];
__device__ float    g_part[NB][5][NBLK];
__device__ unsigned g_barcnt;
__device__ volatile unsigned g_sense;
__device__ unsigned g_taskctr[4];

struct TileC {                      // conv tasks: 128x64 out, halo-2
    float h1[68][128];
    float e2[68][2];                // [r][0]=h1 col -1, [r][1]=h1 col 128
};
struct TileS2 {                     // stats tasks: 128x32 out, x AND y tiles
    float h1x[36][128];
    float h1y[36][128];
    float e2x[36][2], e2y[36][2];
    float red[5][8];
};
#define SMEM_BYTES (sizeof(TileS2) > sizeof(TileC) ? sizeof(TileS2) : sizeof(TileC))

__inline__ __device__ float warpSumF(float v) {
#pragma unroll
    for (int o = 16; o; o >>= 1) v += __shfl_down_sync(WFULL, v, o);
    return v;
}
__inline__ __device__ double warpSumD(double v) {
#pragma unroll
    for (int o = 16; o; o >>= 1) v += __shfl_down_sync(WFULL, v, o);
    return v;
}

__device__ __forceinline__ float4 vpass(float4 a, float4 b, float4 c) {
    return make_float4(P_ * (a.x + c.x) + Q_ * b.x,
                       P_ * (a.y + c.y) + Q_ * b.y,
                       P_ * (a.z + c.z) + Q_ * b.z,
                       P_ * (a.w + c.w) + Q_ * b.w);
}

// ---- row load: thread's float4 of row gy + edge scalars for lanes 0/31 ----
// Edges come from ONE predicated LDG.128 with per-lane addresses:
//   lane 0  -> cols x0-4 .. x0-1   (predicate x0 > 0;     all in-bounds)
//   lane 31 -> cols x0+128..x0+131 (predicate x0 < WW-128; x0<=768 -> <=899)
// NCH==3: raw inputs (immutable) -> cached loads. NCH==1: ping-pong scratch
// written by other SMs across the software barrier -> __ldcg (L1 incoherent).
template <int NCH>
__device__ __forceinline__ float4 load_row(const float* __restrict__ s, int gy,
                                           int x0, int lane, float& e0, float& e1) {
    e0 = 0.f; e1 = 0.f;
    if ((unsigned)gy >= HH) return make_float4(0.f, 0.f, 0.f, 0.f);
    const float* r = s + (size_t)gy * WW;
    const float* q = r + x0 + lane * 4;
    float4 a;
    if (NCH == 3) {
        a = *(const float4*)q;
        float4 b = *(const float4*)(q + NPIX);
        float4 c = *(const float4*)(q + 2 * NPIX);
        a.x += b.x + c.x; a.y += b.y + c.y; a.z += b.z + c.z; a.w += b.w + c.w;
    } else {
        a = __ldcg((const float4*)q);
    }
    const bool pe = (lane == 0) ? (x0 > 0)
                  : ((lane == 31) ? (x0 < WW - 128) : false);
    float4 E = make_float4(0.f, 0.f, 0.f, 0.f);
    const float* ea = r + x0 + ((lane == 31) ? 128 : -4);
    if (pe) {
        if (NCH == 3) {
            float4 A = *(const float4*)ea;
            float4 B = *(const float4*)(ea + NPIX);
            float4 C = *(const float4*)(ea + 2 * NPIX);
            E = make_float4(A.x + B.x + C.x, A.y + B.y + C.y,
                            A.z + B.z + C.z, A.w + B.w + C.w);
        } else {
            E = __ldcg((const float4*)ea);
        }
    }
    e0 = (lane == 0) ? E.z : E.x;   // lane0: col x0-2 ; lane31: col x0+128
    e1 = (lane == 0) ? E.w : E.y;   // lane0: col x0-1 ; lane31: col x0+129
    return a;
}

// ---- horizontal conv of a register row via shuffles ----------------------
__device__ __forceinline__ float4 hshuf(float4 x, float e0, float e1, int lane) {
    float xl = __shfl_up_sync(WFULL, x.w, 1);   if (lane == 0)  xl = e1;
    float xr = __shfl_down_sync(WFULL, x.x, 1); if (lane == 31) xr = e0;
    return make_float4(P_ * (xl + x.y) + Q_ * x.x,
                       P_ * (x.x + x.z) + Q_ * x.y,
                       P_ * (x.y + x.w) + Q_ * x.z,
                       P_ * (x.z + xr) + Q_ * x.w);
}

// ---- generic h1 store (NR rows), branch-free unified edge math ------------
template <int NCH, int NR, bool EDGES>
__device__ __forceinline__ void h1_store(float (*h1)[128], float (*e2)[2],
                                         const float* __restrict__ src,
                                         int x0, int ytop, int lane, int w) {
#pragma unroll
    for (int k = 0; k < (NR + 7) / 8; k++) {
        int r = w + 8 * k;
        if (r < NR) {
            float e0, e1;
            float4 x = load_row<NCH>(src, ytop + r, x0, lane, e0, e1);
            *(float4*)&h1[r][4 * lane] = hshuf(x, e0, e1, lane);
            if (EDGES) {
                // lane0: h1(col -1) = P*(e0 + x.x) + Q*e1
                // lane31: h1(col 128) = P*(x.w + e1) + Q*e0
                float sA = (lane == 0) ? e0 : x.w;
                float sB = (lane == 0) ? x.x : e1;
                float sC = (lane == 0) ? e1 : e0;
                float ev = P_ * (sA + sB) + Q_ * sC;
                if (lane == 0 || lane == 31) e2[r][(lane == 0) ? 0 : 1] = ev;
            }
        }
    }
}

// ---- h2 row rv (gv = y0-1+rv) from h1 rows rv..rv+2 -----------------------
__device__ __forceinline__ float4 h2row_ld(const float (*h1)[128],
                                           const float (*e2)[2],
                                           int rv, int y0, int lane,
                                           bool xlo, bool xhi) {
    float4 a0 = *(float4*)&h1[rv][4 * lane];
    float4 a1 = *(float4*)&h1[rv + 1][4 * lane];
    float4 a2 = *(float4*)&h1[rv + 2][4 * lane];
    float4 v = vpass(a0, a1, a2);
    const int side = (lane == 31) ? 1 : 0;   // lanes 1..30 harmlessly read side 0
    float ve = P_ * (e2[rv][side] + e2[rv + 2][side]) + Q_ * e2[rv + 1][side];
    int gv = y0 - 1 + rv;
    if ((unsigned)gv >= HH) { v = make_float4(0.f, 0.f, 0.f, 0.f); ve = 0.f; }
    if (lane == 0 && xlo)  ve = 0.f;   // col -1 outside image
    if (lane == 31 && xhi) ve = 0.f;   // col 1024 outside image
    float vl = __shfl_up_sync(WFULL, v.w, 1);   if (lane == 0)  vl = ve;
    float vr = __shfl_down_sync(WFULL, v.x, 1); if (lane == 31) vr = ve;
    float4 g;
    g.x = P_ * (vl + v.y) + Q_ * v.x;
    g.y = P_ * (v.x + v.z) + Q_ * v.y;
    g.z = P_ * (v.y + v.w) + Q_ * v.z;
    g.w = P_ * (v.z + vr) + Q_ * v.w;
    return g;
}

// ---- conv epilogue: warp w writes output rows y0+8w .. y0+8w+7 ------------
__device__ void conv_epi(TileC* S, float* __restrict__ dst, int x0, int y0,
                         int lane, int w, bool xlo, bool xhi) {
    const int base = 8 * w;
    float4 g0 = h2row_ld(S->h1, S->e2, base, y0, lane, xlo, xhi);
    float4 g1 = h2row_ld(S->h1, S->e2, base + 1, y0, lane, xlo, xhi);
#pragma unroll
    for (int j = 0; j < 8; j++) {
        float4 g2 = h2row_ld(S->h1, S->e2, base + j + 2, y0, lane, xlo, xhi);
        float4 o = vpass(g0, g1, g2);
        *(float4*)(dst + (size_t)(y0 + base + j) * WW + x0 + 4 * lane) = o;
        g0 = g1; g1 = g2;
    }
}

// ---- moments ---------------------------------------------------------------
__device__ __forceinline__ void mom_acc(float4 a, float4 b, float& su, float& su2,
                                        float& sv, float& sv2, float& suv) {
    su  += a.x + a.y + a.z + a.w;
    su2 += a.x * a.x + a.y * a.y + a.z * a.z + a.w * a.w;
    sv  += b.x + b.y + b.z + b.w;
    sv2 += b.x * b.x + b.y * b.y + b.z * b.z + b.w * b.w;
    suv += a.x * b.x + a.y * b.y + a.z * b.z + a.w * b.w;
}

// ---- stats epilogue, double conv: fused x+y rolling g-windows -------------
__device__ void stats_epi_double(TileS2* S, int y0, int lane, int w,
                                 bool xlo, bool xhi, float& su, float& su2,
                                 float& sv, float& sv2, float& suv) {
    const int b = 4 * w;
    float4 gx0, gx1, gy0, gy1;
#pragma unroll
    for (int m = 0; m < 6; m++) {
        const int rv = b + m;
        float4 gx2 = h2row_ld(S->h1x, S->e2x, rv, y0, lane, xlo, xhi);
        float4 gy2 = h2row_ld(S->h1y, S->e2y, rv, y0, lane, xlo, xhi);
        if (m >= 2) {
            float4 ox = vpass(gx0, gx1, gx2);
            float4 oy = vpass(gy0, gy1, gy2);
            mom_acc(ox, oy, su, su2, sv, sv2, suv);
        }
        gx0 = gx1; gx1 = gx2; gy0 = gy1; gy1 = gy2;
    }
}

// ---- stats epilogue, single conv -------------------------------------------
__device__ void stats_epi_single(TileS2* S, int lane, int w, float& su, float& su2,
                                 float& sv, float& sv2, float& suv) {
    const int b = 4 * w;
#pragma unroll
    for (int j = 0; j < 4; j++) {
        float4 ax0 = *(float4*)&S->h1x[b + j][4 * lane];
        float4 ax1 = *(float4*)&S->h1x[b + j + 1][4 * lane];
        float4 ax2 = *(float4*)&S->h1x[b + j + 2][4 * lane];
        float4 ox = vpass(ax0, ax1, ax2);
        float4 ay0 = *(float4*)&S->h1y[b + j][4 * lane];
        float4 ay1 = *(float4*)&S->h1y[b + j + 1][4 * lane];
        float4 ay2 = *(float4*)&S->h1y[b + j + 2][4 * lane];
        float4 oy = vpass(ay0, ay1, ay2);
        mom_acc(ox, oy, su, su2, sv, sv2, suv);
    }
}

// ---- global software barrier ---------------------------------------------
__device__ __forceinline__ void gbar(int nblocks, unsigned phase, int tid) {
    __syncthreads();
    if (tid == 0) {
        __threadfence();
        unsigned c = atomicAdd(&g_barcnt, 1u);
        if (c == (unsigned)nblocks - 1u) {
            g_barcnt = 0;
            __threadfence();
            g_sense = phase;
        } else {
            while (g_sense < phase) __nanosleep(64);
            __threadfence();
        }
    }
    __syncthreads();
}

// ---- finalize: 8 SSIM terms in double (block 0) --------------------------
__device__ void finalize_dev(float* __restrict__ out, int tid) {
    __shared__ double smd[NB][5];
    const int w = tid >> 5, lane = tid & 31;
    for (int idx = w; idx < NB * 5; idx += 8) {
        int t = idx / 5, m = idx - 5 * t;
        double s = 0.0;
        for (int b = lane; b < NBLK; b += 32)
            s += (double)__ldcg(&g_part[t][m][b]);   // cross-SM data: bypass L1
        s = warpSumD(s);
        if (lane == 0) smd[t][m] = s;
    }
    __syncthreads();
    if (tid == 0) {
        double tot = 0.0, sc = 1.0;
        const double N = (double)NPIX;
        const double C1 = 6.5025;    // (0.01*255)^2
        const double C2 = 58.5225;   // (0.03*255)^2
        for (int t = 0; t < NB; t++) {
            double SU = smd[t][0], SU2 = smd[t][1], SV = smd[t][2],
                   SV2 = smd[t][3], SUV = smd[t][4];
            double mu = sc * SU / N;
            double mv = sc * SV / N;
            double varu = sc * sc * (SU2 - SU * SU / N) / (N - 1.0);
            double varv = sc * sc * (SV2 - SV * SV / N) / (N - 1.0);
            double cov  = sc * sc * (SUV - SU * SV / N) / (N - 1.0);
            tot += ((2.0 * mu * mv + C1) * (2.0 * cov + C2)) /
                   ((mu * mu + mv * mv + C1) * (varu * varu + varv * varv + C2));
            sc *= 3.0;   // 3^t channel-mixing gain
        }
        out[0] = (float)tot;
    }
}

// ---------------------------------------------------------------------------
// Persistent kernel: 4 pair-phases with global barriers; work-stealing with
// pipelined ticket fetch. R14 config (48 regs / 5 blocks) + vectorized edges.
// ---------------------------------------------------------------------------
__global__ void __launch_bounds__(256, 5)
ssim_persist(const float* __restrict__ xin, const float* __restrict__ yin,
             float* __restrict__ out, int nblocks) {
    __shared__ __align__(16) char smem_raw[SMEM_BYTES];
    __shared__ unsigned s_task;
    TileC*  Sc = (TileC*)smem_raw;
    TileS2* Ss = (TileS2*)smem_raw;
    const int tid = threadIdx.x, lane = tid & 31, w = tid >> 5;

    for (int p = 0; p < 4; p++) {
        const int t0 = 2 * p, nimg = NB - t0;
        const int rp = (p & 1) ^ 1, wp = p & 1;
        const unsigned nstats = 2u * NBLK;
        const unsigned ntasks = nstats + (unsigned)(2 * (nimg - 2)) * NCONVT;

        if (tid == 0) s_task = atomicAdd(&g_taskctr[p], 1u);
        __syncthreads();
        unsigned task = s_task;

        while (task < ntasks) {
            if (task >= nstats) {
                // ---- conv task: 128x64 tile ----
                const unsigned ct = task - nstats;
                const int plane2 = (int)(ct >> 7), tile = (int)(ct & 127);
                const int x0 = (tile & 7) * 128;
                const int y0 = (tile >> 3) * 64;
                const bool xlo = (x0 == 0), xhi = (x0 == WW - 128);
                int xy = (plane2 >= nimg - 2) ? 1 : 0;
                int img = t0 + 2 + plane2 - xy * (nimg - 2);
                const float* src = (p == 0)
                    ? ((xy ? yin : xin) + (size_t)img * 3 * NPIX)
                    : (g_buf[rp][xy] + (size_t)img * NPIX);
                float* dst = g_buf[wp][xy] + (size_t)img * NPIX;

                if (p == 0) h1_store<3, 68, true>(Sc->h1, Sc->e2, src, x0, y0 - 2, lane, w);
                else        h1_store<1, 68, true>(Sc->h1, Sc->e2, src, x0, y0 - 2, lane, w);
                if (tid == 0) s_task = atomicAdd(&g_taskctr[p], 1u);  // pipelined
                __syncthreads();   // h1 ready + ticket published
                conv_epi(Sc, dst, x0, y0, lane, w, xlo, xhi);
                unsigned nxt = s_task;
                __syncthreads();   // epilogue done; smem free for next task
                task = nxt;
            } else {
                // ---- stats task: 128x32 tile, x & y fused ----
                const int plane = (int)(task >> 8), tile = (int)(task & 255);
                const int x0 = (tile & 7) * 128;
                const int y0 = (tile >> 3) * 32;
                const bool xlo = (x0 == 0), xhi = (x0 == WW - 128);
                const int t = t0 + plane;
                const float *sx, *sy;
                if (p == 0) {
                    sx = xin + (size_t)t * 3 * NPIX;
                    sy = yin + (size_t)t * 3 * NPIX;
                } else {
                    sx = g_buf[rp][0] + (size_t)t * NPIX;
                    sy = g_buf[rp][1] + (size_t)t * NPIX;
                }
                if (plane == 0) {
                    if (p == 0) {
                        h1_store<3, 34, false>(Ss->h1x, Ss->e2x, sx, x0, y0 - 1, lane, w);
                        h1_store<3, 34, false>(Ss->h1y, Ss->e2y, sy, x0, y0 - 1, lane, w);
                    } else {
                        h1_store<1, 34, false>(Ss->h1x, Ss->e2x, sx, x0, y0 - 1, lane, w);
                        h1_store<1, 34, false>(Ss->h1y, Ss->e2y, sy, x0, y0 - 1, lane, w);
                    }
                } else {
                    if (p == 0) {
                        h1_store<3, 36, true>(Ss->h1x, Ss->e2x, sx, x0, y0 - 2, lane, w);
                        h1_store<3, 36, true>(Ss->h1y, Ss->e2y, sy, x0, y0 - 2, lane, w);
                    } else {
                        h1_store<1, 36, true>(Ss->h1x, Ss->e2x, sx, x0, y0 - 2, lane, w);
                        h1_store<1, 36, true>(Ss->h1y, Ss->e2y, sy, x0, y0 - 2, lane, w);
                    }
                }
                if (tid == 0) s_task = atomicAdd(&g_taskctr[p], 1u);  // pipelined
                __syncthreads();   // both h1 tiles ready + ticket published

                float su = 0, su2 = 0, sv = 0, sv2 = 0, suv = 0;
                if (plane == 0) stats_epi_single(Ss, lane, w, su, su2, sv, sv2, suv);
                else stats_epi_double(Ss, y0, lane, w, xlo, xhi, su, su2, sv, sv2, suv);

                su = warpSumF(su); su2 = warpSumF(su2); sv = warpSumF(sv);
                sv2 = warpSumF(sv2); suv = warpSumF(suv);
                if (lane == 0) {
                    Ss->red[0][w] = su; Ss->red[1][w] = su2; Ss->red[2][w] = sv;
                    Ss->red[3][w] = sv2; Ss->red[4][w] = suv;
                }
                unsigned nxt = s_task;
                __syncthreads();   // red ready; epilogue done; smem free next
                if (tid < 5) {
                    float r = 0.f;
#pragma unroll
                    for (int q = 0; q < 8; q++) r += Ss->red[tid][q];
                    g_part[t][tid][tile] = r;
                }
                task = nxt;
            }
        }
        gbar(nblocks, (unsigned)(p + 1), tid);
    }

    if (blockIdx.x == 0) {
        finalize_dev(out, tid);
        if (tid == 0) {
            g_taskctr[0] = 0; g_taskctr[1] = 0;
            g_taskctr[2] = 0; g_taskctr[3] = 0;
            __threadfence();
            g_sense = 0;   // reset for next graph replay
        }
    }
}

// ---------------------------------------------------------------------------
extern "C" void kernel_launch(void* const* d_in, const int* in_sizes, int n_in,
                              void* d_out, int out_size) {
    const float* x = (const float*)d_in[0];
    const float* y = (const float*)d_in[1];
    float* out = (float*)d_out;

    int dev = 0;
    cudaGetDevice(&dev);
    int sms = 148;
    cudaDeviceGetAttribute(&sms, cudaDevAttrMultiProcessorCount, dev);
    int occ = 1;
    cudaOccupancyMaxActiveBlocksPerMultiprocessor(&occ, ssim_persist, 256, 0);
    if (occ < 1) occ = 1;
    int nblocks = sms * occ;

    ssim_persist<<<nblocks, 256>>>(x, y, out, nblocks);
}